// round 15
// baseline (speedup 1.0000x reference)
#include <cuda_runtime.h>
#include <cuda_fp16.h>
#include <cstdint>
#include <cstddef>

#define D_IN    256
#define H_DIM   512
#define DO_DIM  256
#define B_GR    64

#define BM  64
#define BN  128
#define BK  64
#define E_MAX 200064

#define A_BYTES (BM * BK * 2)                 // 8192 (fp16 in smem)
#define B_BYTES (BN * BK * 2)                 // 16384
#define STAGE_BYTES (A_BYTES + B_BYTES)       // 24576
#define SMEM_G1 (2 * STAGE_BYTES)             // 49152 -> 3 CTAs/SM
#define SMEM_G2 (3 * STAGE_BYTES)             // 73728 -> 3 CTAs/SM

// Allocation-free scratch
__device__ __half g_hh[(size_t)E_MAX * H_DIM];        // fp16 activations
__device__ float  g_ug[B_GR * H_DIM];
__device__ int    g_bidx[E_MAX];
__device__ __half g_w1h[(size_t)H_DIM * (3 * D_IN)];  // W1^T [n=512][k=768] fp16
__device__ __half g_w2h[(size_t)DO_DIM * H_DIM];      // W2^T [n=256][k=512] fp16

__device__ __forceinline__ void mma_f16(float* c, const uint32_t* a, const uint32_t* b) {
    asm volatile(
        "mma.sync.aligned.m16n8k16.row.col.f32.f16.f16.f32 "
        "{%0,%1,%2,%3}, {%4,%5,%6,%7}, {%8,%9}, {%0,%1,%2,%3};\n"
        : "+f"(c[0]), "+f"(c[1]), "+f"(c[2]), "+f"(c[3])
        : "r"(a[0]), "r"(a[1]), "r"(a[2]), "r"(a[3]), "r"(b[0]), "r"(b[1]));
}
__device__ __forceinline__ void ldsm4(uint32_t* r, uint32_t saddr) {
    asm volatile("ldmatrix.sync.aligned.m8n8.x4.shared.b16 {%0,%1,%2,%3}, [%4];"
                 : "=r"(r[0]), "=r"(r[1]), "=r"(r[2]), "=r"(r[3]) : "r"(saddr));
}
__device__ __forceinline__ void cp16(uint32_t saddr, const void* gaddr, uint32_t sz) {
    asm volatile("cp.async.cg.shared.global [%0], [%1], 16, %2;\n"
                 :: "r"(saddr), "l"(gaddr), "r"(sz));
}
__device__ __forceinline__ void cp_commit() { asm volatile("cp.async.commit_group;\n"); }
template <int N>
__device__ __forceinline__ void cp_wait() { asm volatile("cp.async.wait_group %0;\n" :: "n"(N)); }
__device__ __forceinline__ void sts64(uint32_t saddr, uint32_t v0, uint32_t v1) {
    asm volatile("st.shared.v2.b32 [%0], {%1,%2};" :: "r"(saddr), "r"(v0), "r"(v1));
}

// ---------------------------------------------------------------------------
// batch index normalization (int32 or int64 source) -> g_bidx
// ---------------------------------------------------------------------------
__global__ void bidx_kernel(const int* __restrict__ batch32, int E) {
    const int tid = threadIdx.x;
    __shared__ int s_is64;
    bool ok = true;
    if (tid < 128) {
        int lo = batch32[2 * tid];
        int hi = batch32[2 * tid + 1];
        ok = (hi == 0) && (lo >= 0) && (lo < B_GR);
    }
    unsigned m = __ballot_sync(0xFFFFFFFFu, ok);
    __shared__ unsigned s_votes[8];
    if ((tid & 31) == 0) s_votes[tid >> 5] = m;
    __syncthreads();
    if (tid == 0) {
        bool all = true;
        for (int w = 0; w < 4; w++) all = all && (s_votes[w] == 0xFFFFFFFFu);
        s_is64 = all ? 1 : 0;
    }
    __syncthreads();
    const int is64 = s_is64;
    for (int e = blockIdx.x * blockDim.x + tid; e < E; e += gridDim.x * blockDim.x) {
        int v = is64 ? batch32[2 * e] : batch32[e];
        g_bidx[e] = v & (B_GR - 1);
    }
}

// ---------------------------------------------------------------------------
// Weight prep: transpose to [n][k] + fp16 round (once; small)
// ---------------------------------------------------------------------------
__global__ void prep_w(const float* __restrict__ W1, const float* __restrict__ W2) {
    const size_t n1 = (size_t)H_DIM * (3 * D_IN);
    const size_t n2 = (size_t)DO_DIM * H_DIM;
    for (size_t i = (size_t)blockIdx.x * blockDim.x + threadIdx.x; i < n1 + n2;
         i += (size_t)gridDim.x * blockDim.x) {
        if (i < n1) {
            int n = (int)(i / (3 * D_IN));
            int k = (int)(i % (3 * D_IN));
            g_w1h[i] = __float2half_rn(W1[(size_t)k * H_DIM + n]);
        } else {
            size_t o = i - n1;
            int n = (int)(o / H_DIM);
            int k = (int)(o % H_DIM);
            g_w2h[o] = __float2half_rn(W2[(size_t)k * DO_DIM + n]);
        }
    }
}

// ---------------------------------------------------------------------------
// ug[b][n] = b1[n] + sum_k u[b][k] * W1[768+k][n]  (fp32)
// ---------------------------------------------------------------------------
__global__ void ug_kernel(const float* __restrict__ u, const float* __restrict__ W1,
                          const float* __restrict__ b1) {
    const int b = blockIdx.x;
    const int n = blockIdx.y * 128 + threadIdx.x;
    __shared__ float us[D_IN];
    for (int i = threadIdx.x; i < D_IN; i += 128) us[i] = u[b * D_IN + i];
    __syncthreads();
    float acc = b1[n];
    #pragma unroll 8
    for (int k = 0; k < D_IN; k++)
        acc += us[k] * W1[(size_t)(3 * D_IN + k) * H_DIM + n];
    g_ug[b * H_DIM + n] = acc;
}

// ---------------------------------------------------------------------------
// GEMM1: h = relu(cat(src,dest,edge)@W1abc + ug[bidx]) -> g_hh (fp16)
// A staged from fp32 sources via LDG.128 + cvt + STS (no prep pass);
// B via cp.async. 2-stage double buffer, two syncs/tile. 3 CTAs/SM.
// CTA 64x128x64, 8 warps (2m x 4n, warp tile 32x32), m16n8k16.
// ---------------------------------------------------------------------------
__global__ void __launch_bounds__(256, 3)
gemm1_kernel(const float* __restrict__ A0, const float* __restrict__ A1,
             const float* __restrict__ A2, int E) {
    extern __shared__ __half smem[];
    const uint32_t sbase = (uint32_t)__cvta_generic_to_shared(smem);
    // layout: [A0 | A1 | B0 | B1]
    const uint32_t sA0 = sbase;
    const uint32_t sB0 = sbase + 2 * A_BYTES;

    const int e0 = blockIdx.y * BM;
    const int n0 = blockIdx.x * BN;

    const int tid  = threadIdx.x;
    const int lane = tid & 31;
    const int warp = tid >> 5;
    const int wRow = (warp >> 2) * 32;
    const int wCol = (warp & 3) * 32;

    float c[2][4][4];
    #pragma unroll
    for (int mt = 0; mt < 2; mt++)
        #pragma unroll
        for (int nt = 0; nt < 4; nt++)
            #pragma unroll
            for (int i = 0; i < 4; i++) c[mt][nt][i] = 0.f;

    // ldmatrix lane maps (128B rows; swizzled chunk = ch ^ (row&7))
    int aR[2], aR7[2];
    #pragma unroll
    for (int mt = 0; mt < 2; mt++) {
        aR[mt]  = wRow + mt * 16 + (lane & 15);
        aR7[mt] = aR[mt] & 7;
    }
    const int aCb = lane >> 4;
    int bR[2], bR7[2];
    #pragma unroll
    for (int pp = 0; pp < 2; pp++) {
        bR[pp]  = wCol + pp * 16 + ((lane & 16) ? 8 : 0) + (lane & 7);
        bR7[pp] = bR[pp] & 7;
    }
    const int bCb = (lane >> 3) & 1;

    // A LDG/STS map: row = tid>>2 (0..63), float4-chunk = (tid&3) + 4j (j<4)
    const int aRow = tid >> 2;
    const int aCk0 = tid & 3;
    // B cp.async map: row = tid>>1 (0..127), 16B-chunk = (tid&1)*4 + j (j<4)
    const int bSRow = tid >> 1;
    const int bSC   = (tid & 1) * 4;

    const int eRow = e0 + aRow;
    const int eClamp = (eRow < E) ? eRow : (E - 1);

    constexpr int KT = (3 * D_IN) / BK;   // 12

    auto ldgA = [&](int kt, float4* v) {
        const int kg = kt * BK;
        const float* Ap = (kg < 256) ? A0 : (kg < 512) ? A1 : A2;
        const int kin = kg & 255;
        const float* row = Ap + (size_t)eClamp * D_IN + kin;
        #pragma unroll
        for (int j = 0; j < 4; j++)
            v[j] = *(const float4*)&row[(aCk0 + 4 * j) * 4];
    };
    auto stsA = [&](int slot, const float4* v) {
        const uint32_t sA = sA0 + (uint32_t)slot * A_BYTES;
        #pragma unroll
        for (int j = 0; j < 4; j++) {
            const int chunk = aCk0 + 4 * j;          // float4 index (16 per row)
            const int ch16  = chunk >> 1;            // fp16 16B-chunk (8 per row)
            const uint32_t off = (uint32_t)(aRow * 128 + ((ch16 ^ (aRow & 7)) << 4)
                                            + (chunk & 1) * 8);
            uint32_t h01 = (uint32_t)__half2_raw(__floats2half2_rn(v[j].x, v[j].y)).x |
                           ((uint32_t)__half2_raw(__floats2half2_rn(v[j].x, v[j].y)).y << 16);
            uint32_t h23 = (uint32_t)__half2_raw(__floats2half2_rn(v[j].z, v[j].w)).x |
                           ((uint32_t)__half2_raw(__floats2half2_rn(v[j].z, v[j].w)).y << 16);
            sts64(sA + off, h01, h23);
        }
    };
    auto stageB = [&](int kt, int slot) {
        const int kg = kt * BK;
        const uint32_t sB = sB0 + (uint32_t)slot * B_BYTES;
        #pragma unroll
        for (int j = 0; j < 4; j++) {
            const int ch = bSC + j;
            const uint32_t so = (uint32_t)(bSRow * 128 + (ch ^ (bSRow & 7)) * 16);
            cp16(sB + so, g_w1h + (size_t)(n0 + bSRow) * (3 * D_IN) + kg + ch * 8, 16u);
        }
        cp_commit();
    };

    // Prologue: tile 0 fully staged
    {
        float4 v[4];
        ldgA(0, v);
        stsA(0, v);
        stageB(0, 0);
    }

    float4 aNext[4];
    for (int kt = 0; kt < KT; kt++) {
        if (kt + 1 < KT) {
            ldgA(kt + 1, aNext);                 // LDGs fly under wait+compute
            stageB(kt + 1, (kt + 1) & 1);
            cp_wait<1>();
        } else {
            cp_wait<0>();
        }
        __syncthreads();                         // B(kt) landed; A(kt) STS visible

        const uint32_t sA = sA0 + (uint32_t)(kt & 1) * A_BYTES;
        const uint32_t sB = sB0 + (uint32_t)(kt & 1) * B_BYTES;

        #pragma unroll
        for (int t = 0; t < 4; t++) {
            const int kc = t * 2;
            uint32_t a[2][4];
            uint32_t b[2][4];
            #pragma unroll
            for (int mt = 0; mt < 2; mt++)
                ldsm4(a[mt], sA + (uint32_t)(aR[mt] * 128 + (((kc + aCb) ^ aR7[mt]) << 4)));
            #pragma unroll
            for (int pp = 0; pp < 2; pp++)
                ldsm4(b[pp], sB + (uint32_t)(bR[pp] * 128 + (((kc + bCb) ^ bR7[pp]) << 4)));
            #pragma unroll
            for (int mt = 0; mt < 2; mt++)
                #pragma unroll
                for (int nt = 0; nt < 4; nt++)
                    mma_f16(c[mt][nt], a[mt], &b[nt >> 1][(nt & 1) * 2]);
        }

        if (kt + 1 < KT) stsA((kt + 1) & 1, aNext);   // cvt+STS after compute
        __syncthreads();                              // WAR + publish A(kt+1)
    }

    // Epilogue: + ug[bidx], ReLU -> g_hh (fp16)
    #pragma unroll
    for (int mt = 0; mt < 2; mt++) {
        #pragma unroll
        for (int half = 0; half < 2; half++) {
            int r = wRow + mt * 16 + (lane >> 2) + half * 8;
            int e = e0 + r;
            if (e >= E) continue;
            int bg = g_bidx[e];
            const float* ugr = &g_ug[(size_t)bg * H_DIM + n0];
            __half*      hr  = &g_hh[(size_t)e * H_DIM + n0];
            #pragma unroll
            for (int nt = 0; nt < 4; nt++) {
                int col = wCol + nt * 8 + (lane & 3) * 2;
                float2 g = *(const float2*)&ugr[col];
                float ox = fmaxf(c[mt][nt][half * 2 + 0] + g.x, 0.f);
                float oy = fmaxf(c[mt][nt][half * 2 + 1] + g.y, 0.f);
                *(__half2*)&hr[col] = __floats2half2_rn(ox, oy);
            }
        }
    }
}

// ---------------------------------------------------------------------------
// GEMM2: out = g_hh @ W2 + b2 (fp32 out). 3-stage cp.async, single sync/tile.
// ---------------------------------------------------------------------------
__global__ void __launch_bounds__(256, 3)
gemm2_kernel(const float* __restrict__ bias2, float* __restrict__ out, int E) {
    extern __shared__ __half smem[];
    const uint32_t sbase = (uint32_t)__cvta_generic_to_shared(smem);

    const int e0 = blockIdx.y * BM;
    const int n0 = blockIdx.x * BN;

    const int tid  = threadIdx.x;
    const int lane = tid & 31;
    const int warp = tid >> 5;
    const int wRow = (warp >> 2) * 32;
    const int wCol = (warp & 3) * 32;

    float c[2][4][4];
    #pragma unroll
    for (int mt = 0; mt < 2; mt++)
        #pragma unroll
        for (int nt = 0; nt < 4; nt++)
            #pragma unroll
            for (int i = 0; i < 4; i++) c[mt][nt][i] = 0.f;

    int aR[2], aR7[2];
    #pragma unroll
    for (int mt = 0; mt < 2; mt++) {
        aR[mt]  = wRow + mt * 16 + (lane & 15);
        aR7[mt] = aR[mt] & 7;
    }
    const int aCb = lane >> 4;
    int bR[2], bR7[2];
    #pragma unroll
    for (int pp = 0; pp < 2; pp++) {
        bR[pp]  = wCol + pp * 16 + ((lane & 16) ? 8 : 0) + (lane & 7);
        bR7[pp] = bR[pp] & 7;
    }
    const int bCb = (lane >> 3) & 1;

    const int aSRow = tid >> 2;
    const int aSC   = (tid & 3) * 2;
    const int bSRow = tid >> 1;
    const int bSC   = (tid & 1) * 4;

    constexpr int KT = H_DIM / BK;   // 8

    auto stage = [&](int kt, int slot) {
        const int kg = kt * BK;
        const uint32_t sA = sbase + (uint32_t)slot * STAGE_BYTES;
        const uint32_t sB = sA + A_BYTES;
        #pragma unroll
        for (int j = 0; j < 2; j++) {
            const int ch = aSC + j;
            const uint32_t so = (uint32_t)(aSRow * 128 + (ch ^ (aSRow & 7)) * 16);
            const int e = e0 + aSRow;
            const int ec = (e < E) ? e : 0;
            cp16(sA + so, g_hh + (size_t)ec * H_DIM + kg + ch * 8, (e < E) ? 16u : 0u);
        }
        #pragma unroll
        for (int j = 0; j < 4; j++) {
            const int ch = bSC + j;
            const uint32_t so = (uint32_t)(bSRow * 128 + (ch ^ (bSRow & 7)) * 16);
            cp16(sB + so, g_w2h + (size_t)(n0 + bSRow) * H_DIM + kg + ch * 8, 16u);
        }
        cp_commit();
    };

    stage(0, 0);
    stage(1, 1);

    int rd = 0;
    for (int kt = 0; kt < KT; kt++) {
        if (kt + 1 < KT) cp_wait<1>();
        else             cp_wait<0>();
        __syncthreads();

        int wr = rd + 2; if (wr >= 3) wr -= 3;
        if (kt + 2 < KT) stage(kt + 2, wr);

        const uint32_t sA = sbase + (uint32_t)rd * STAGE_BYTES;
        const uint32_t sB = sA + A_BYTES;

        #pragma unroll
        for (int t = 0; t < 4; t++) {
            const int kc = t * 2;
            uint32_t a[2][4];
            uint32_t b[2][4];
            #pragma unroll
            for (int mt = 0; mt < 2; mt++)
                ldsm4(a[mt], sA + (uint32_t)(aR[mt] * 128 + (((kc + aCb) ^ aR7[mt]) << 4)));
            #pragma unroll
            for (int pp = 0; pp < 2; pp++)
                ldsm4(b[pp], sB + (uint32_t)(bR[pp] * 128 + (((kc + bCb) ^ bR7[pp]) << 4)));
            #pragma unroll
            for (int mt = 0; mt < 2; mt++)
                #pragma unroll
                for (int nt = 0; nt < 4; nt++)
                    mma_f16(c[mt][nt], a[mt], &b[nt >> 1][(nt & 1) * 2]);
        }

        rd = rd + 1; if (rd >= 3) rd -= 3;
    }

    #pragma unroll
    for (int mt = 0; mt < 2; mt++) {
        #pragma unroll
        for (int half = 0; half < 2; half++) {
            int r = wRow + mt * 16 + (lane >> 2) + half * 8;
            int e = e0 + r;
            if (e >= E) continue;
            float* orow = &out[(size_t)e * DO_DIM + n0];
            #pragma unroll
            for (int nt = 0; nt < 4; nt++) {
                int col = wCol + nt * 8 + (lane & 3) * 2;
                float2 bb = *(const float2*)&bias2[col + n0];
                float2 o;
                o.x = c[mt][nt][half * 2 + 0] + bb.x;
                o.y = c[mt][nt][half * 2 + 1] + bb.y;
                *(float2*)&orow[col] = o;
            }
        }
    }
}

// ---------------------------------------------------------------------------
// Inputs (metadata order): src, dest, edge_attr, u, batch, W1, b1, W2, b2
// ---------------------------------------------------------------------------
extern "C" void kernel_launch(void* const* d_in, const int* in_sizes, int n_in,
                              void* d_out, int out_size) {
    const float* src   = (const float*)d_in[0];
    const float* dest  = (const float*)d_in[1];
    const float* edge  = (const float*)d_in[2];
    const float* u     = (const float*)d_in[3];
    const int*   batch = (const int*)d_in[4];
    const float* W1    = (const float*)d_in[5];
    const float* b1    = (const float*)d_in[6];
    const float* W2    = (const float*)d_in[7];
    const float* b2    = (const float*)d_in[8];
    float* out = (float*)d_out;

    const int E  = in_sizes[4];
    const int EB = (E + BM - 1) / BM;

    static bool attr_set = false;
    if (!attr_set) {
        cudaFuncSetAttribute(gemm1_kernel, cudaFuncAttributeMaxDynamicSharedMemorySize, SMEM_G1);
        cudaFuncSetAttribute(gemm2_kernel, cudaFuncAttributeMaxDynamicSharedMemorySize, SMEM_G2);
        attr_set = true;
    }

    bidx_kernel<<<256, 256>>>(batch, E);
    prep_w<<<256, 256>>>(W1, W2);
    ug_kernel<<<dim3(B_GR, 4), 128>>>(u, W1, b1);

    dim3 g1(H_DIM / BN, EB);     // n-tiles adjacent -> A rows shared via L2
    gemm1_kernel<<<g1, 256, SMEM_G1>>>(src, dest, edge, E);

    dim3 g2(DO_DIM / BN, EB);
    gemm2_kernel<<<g2, 256, SMEM_G2>>>(b2, out, E);
}

// round 16
// speedup vs baseline: 1.0721x; 1.0721x over previous
#include <cuda_runtime.h>
#include <cuda_fp16.h>
#include <cstdint>
#include <cstddef>

#define D_IN    256
#define H_DIM   512
#define DO_DIM  256
#define B_GR    64

#define BM  64
#define BN  128
#define BK  64
#define E_MAX 200064

#define A_BYTES (BM * BK * 2)                // 8192
#define B_BYTES (BN * BK * 2)                // 16384
#define STAGE_BYTES (A_BYTES + B_BYTES)      // 24576
#define STAGES 3
#define SMEM_BYTES (STAGES * STAGE_BYTES)    // 73728 -> 3 CTAs/SM

// Allocation-free scratch
__device__ __half g_x[(size_t)E_MAX * (3 * D_IN)];    // packed fp16 [src|dest|edge]
__device__ __half g_hh[(size_t)E_MAX * H_DIM];        // fp16 activations
__device__ float  g_ug[B_GR * H_DIM];
__device__ int    g_bidx[E_MAX];
__device__ __half g_w1h[(size_t)H_DIM * (3 * D_IN)];  // W1^T [n=512][k=768] fp16
__device__ __half g_w2h[(size_t)DO_DIM * H_DIM];      // W2^T [n=256][k=512] fp16

__device__ __forceinline__ void mma_f16(float* c, const uint32_t* a, const uint32_t* b) {
    asm volatile(
        "mma.sync.aligned.m16n8k16.row.col.f32.f16.f16.f32 "
        "{%0,%1,%2,%3}, {%4,%5,%6,%7}, {%8,%9}, {%0,%1,%2,%3};\n"
        : "+f"(c[0]), "+f"(c[1]), "+f"(c[2]), "+f"(c[3])
        : "r"(a[0]), "r"(a[1]), "r"(a[2]), "r"(a[3]), "r"(b[0]), "r"(b[1]));
}
__device__ __forceinline__ void ldsm4(uint32_t* r, uint32_t saddr) {
    asm volatile("ldmatrix.sync.aligned.m8n8.x4.shared.b16 {%0,%1,%2,%3}, [%4];"
                 : "=r"(r[0]), "=r"(r[1]), "=r"(r[2]), "=r"(r[3]) : "r"(saddr));
}
__device__ __forceinline__ void cp16(uint32_t saddr, const void* gaddr, uint32_t sz) {
    asm volatile("cp.async.cg.shared.global [%0], [%1], 16, %2;\n"
                 :: "r"(saddr), "l"(gaddr), "r"(sz));
}
__device__ __forceinline__ void cp_commit() { asm volatile("cp.async.commit_group;\n"); }
template <int N>
__device__ __forceinline__ void cp_wait() { asm volatile("cp.async.wait_group %0;\n" :: "n"(N)); }

// ---------------------------------------------------------------------------
// batch index normalization (int32 or int64 source) -> g_bidx
// ---------------------------------------------------------------------------
__global__ void bidx_kernel(const int* __restrict__ batch32, int E) {
    const int tid = threadIdx.x;
    __shared__ int s_is64;
    bool ok = true;
    if (tid < 128) {
        int lo = batch32[2 * tid];
        int hi = batch32[2 * tid + 1];
        ok = (hi == 0) && (lo >= 0) && (lo < B_GR);
    }
    unsigned m = __ballot_sync(0xFFFFFFFFu, ok);
    __shared__ unsigned s_votes[8];
    if ((tid & 31) == 0) s_votes[tid >> 5] = m;
    __syncthreads();
    if (tid == 0) {
        bool all = true;
        for (int w = 0; w < 4; w++) all = all && (s_votes[w] == 0xFFFFFFFFu);
        s_is64 = all ? 1 : 0;
    }
    __syncthreads();
    const int is64 = s_is64;
    for (int e = blockIdx.x * blockDim.x + tid; e < E; e += gridDim.x * blockDim.x) {
        int v = is64 ? batch32[2 * e] : batch32[e];
        g_bidx[e] = v & (B_GR - 1);
    }
}

// ---------------------------------------------------------------------------
// Pack src|dest|edge into contiguous fp16 rows g_x[e][768]
// ---------------------------------------------------------------------------
__global__ void prep_x(const float* __restrict__ src, const float* __restrict__ dest,
                       const float* __restrict__ edge, int E) {
    const int total = E * (D_IN / 4);
    for (int i = blockIdx.x * blockDim.x + threadIdx.x; i < total;
         i += gridDim.x * blockDim.x) {
        const int e = i >> 6;
        const int d = (i & 63) * 4;
        const size_t gs = (size_t)e * D_IN + d;
        const size_t go = (size_t)e * (3 * D_IN) + d;
        float4 v;
        v = *(const float4*)&src[gs];
        *(__half2*)&g_x[go + 0] = __floats2half2_rn(v.x, v.y);
        *(__half2*)&g_x[go + 2] = __floats2half2_rn(v.z, v.w);
        v = *(const float4*)&dest[gs];
        *(__half2*)&g_x[go + 256 + 0] = __floats2half2_rn(v.x, v.y);
        *(__half2*)&g_x[go + 256 + 2] = __floats2half2_rn(v.z, v.w);
        v = *(const float4*)&edge[gs];
        *(__half2*)&g_x[go + 512 + 0] = __floats2half2_rn(v.x, v.y);
        *(__half2*)&g_x[go + 512 + 2] = __floats2half2_rn(v.z, v.w);
    }
}

// ---------------------------------------------------------------------------
// Weight prep: transpose to [n][k] + fp16 round (once; small)
// ---------------------------------------------------------------------------
__global__ void prep_w(const float* __restrict__ W1, const float* __restrict__ W2) {
    const size_t n1 = (size_t)H_DIM * (3 * D_IN);
    const size_t n2 = (size_t)DO_DIM * H_DIM;
    for (size_t i = (size_t)blockIdx.x * blockDim.x + threadIdx.x; i < n1 + n2;
         i += (size_t)gridDim.x * blockDim.x) {
        if (i < n1) {
            int n = (int)(i / (3 * D_IN));
            int k = (int)(i % (3 * D_IN));
            g_w1h[i] = __float2half_rn(W1[(size_t)k * H_DIM + n]);
        } else {
            size_t o = i - n1;
            int n = (int)(o / H_DIM);
            int k = (int)(o % H_DIM);
            g_w2h[o] = __float2half_rn(W2[(size_t)k * DO_DIM + n]);
        }
    }
}

// ---------------------------------------------------------------------------
// ug[b][n] = b1[n] + sum_k u[b][k] * W1[768+k][n]  (fp32)
// ---------------------------------------------------------------------------
__global__ void ug_kernel(const float* __restrict__ u, const float* __restrict__ W1,
                          const float* __restrict__ b1) {
    const int b = blockIdx.x;
    const int n = blockIdx.y * 128 + threadIdx.x;
    __shared__ float us[D_IN];
    for (int i = threadIdx.x; i < D_IN; i += 128) us[i] = u[b * D_IN + i];
    __syncthreads();
    float acc = b1[n];
    #pragma unroll 8
    for (int k = 0; k < D_IN; k++)
        acc += us[k] * W1[(size_t)(3 * D_IN + k) * H_DIM + n];
    g_ug[b * H_DIM + n] = acc;
}

// ---------------------------------------------------------------------------
// FP16 GEMM, CTA 64x128x64, 8 warps (2m x 4n, warp tile 32x32), m16n8k16,
// 3-stage cp.async + single sync per tile + register fragment double buffer,
// XOR-swizzled 128B rows, 3 CTAs/SM.
// MODE 1: h = relu(g_x@W1abc + ug[bidx]) -> g_hh (fp16); m-tiles REVERSED so
//         the tail of g_x (still L2-resident from prep_x) is read first.
// MODE 2: out = g_hh @ W2 + b2 (fp32 out); ascending m (gemm1 ends at m=0,
//         so gemm2's first reads hit L2).
// ---------------------------------------------------------------------------
template <int MODE>
__global__ void __launch_bounds__(256, 3)
mlp_gemm(const float* __restrict__ bias2, float* __restrict__ out, int E) {
    extern __shared__ __half smem[];
    const uint32_t sbase = (uint32_t)__cvta_generic_to_shared(smem);

    const int mBlk = (MODE == 1) ? (gridDim.y - 1 - blockIdx.y) : blockIdx.y;
    const int e0 = mBlk * BM;
    const int n0 = blockIdx.x * BN;

    const int tid  = threadIdx.x;
    const int lane = tid & 31;
    const int warp = tid >> 5;
    const int wRow = (warp >> 2) * 32;     // 2 m-groups
    const int wCol = (warp & 3) * 32;      // 4 n-groups

    float c[2][4][4];
    #pragma unroll
    for (int mt = 0; mt < 2; mt++)
        #pragma unroll
        for (int nt = 0; nt < 4; nt++)
            #pragma unroll
            for (int i = 0; i < 4; i++) c[mt][nt][i] = 0.f;

    // ldmatrix lane maps (rows are 128B = 64 halves; swizzled chunk = ch ^ (row&7))
    int aR[2], aR7[2];
    #pragma unroll
    for (int mt = 0; mt < 2; mt++) {
        aR[mt]  = wRow + mt * 16 + (lane & 15);
        aR7[mt] = aR[mt] & 7;
    }
    const int aCb = lane >> 4;             // +0 / +1 chunk
    int bR[2], bR7[2];
    #pragma unroll
    for (int pp = 0; pp < 2; pp++) {
        bR[pp]  = wCol + pp * 16 + ((lane & 16) ? 8 : 0) + (lane & 7);
        bR7[pp] = bR[pp] & 7;
    }
    const int bCb = (lane >> 3) & 1;

    // cp.async staging maps (chunks are 16B = 8 halves)
    const int aSRow = tid >> 2;            // 0..63
    const int aSC   = (tid & 3) * 2;       // +j (j<2)
    const int bSRow = tid >> 1;            // 0..127
    const int bSC   = (tid & 1) * 4;       // +j (j<4)

    constexpr int KT   = (MODE == 1) ? (3 * D_IN) / BK : H_DIM / BK;   // 12 / 8
    constexpr int KDIM = (MODE == 1) ? (3 * D_IN) : H_DIM;

    const __half* Ap = (MODE == 1) ? g_x : g_hh;
    const __half* Bp = (MODE == 1) ? g_w1h : g_w2h;

    auto stage = [&](int kt, int slot) {
        const int kg = kt * BK;
        const uint32_t sA = sbase + (uint32_t)slot * STAGE_BYTES;
        const uint32_t sB = sA + A_BYTES;
        #pragma unroll
        for (int j = 0; j < 2; j++) {
            const int ch = aSC + j;
            const uint32_t so = (uint32_t)(aSRow * 128 + (ch ^ (aSRow & 7)) * 16);
            const int e = e0 + aSRow;
            const int ec = (e < E) ? e : 0;
            cp16(sA + so, Ap + (size_t)ec * KDIM + kg + ch * 8, (e < E) ? 16u : 0u);
        }
        #pragma unroll
        for (int j = 0; j < 4; j++) {
            const int ch = bSC + j;
            const uint32_t so = (uint32_t)(bSRow * 128 + (ch ^ (bSRow & 7)) * 16);
            cp16(sB + so, Bp + (size_t)(n0 + bSRow) * KDIM + kg + ch * 8, 16u);
        }
        cp_commit();
    };

    // Prologue: two tiles in flight
    stage(0, 0);
    stage(1, 1);

    int rd = 0;
    for (int kt = 0; kt < KT; kt++) {
        if (kt + 1 < KT) cp_wait<1>();
        else             cp_wait<0>();
        __syncthreads();

        int wr = rd + 2; if (wr >= STAGES) wr -= STAGES;
        if (kt + 2 < KT) stage(kt + 2, wr);

        const uint32_t sA = sbase + (uint32_t)rd * STAGE_BYTES;
        const uint32_t sB = sA + A_BYTES;

        // Register fragment double buffer across the 4 k16 steps
        uint32_t a[2][2][4];   // [buf][mt][4]
        uint32_t b[2][2][4];   // [buf][pp][4]

        auto ldfrag = [&](int t, int buf) {
            const int kc = t * 2;
            #pragma unroll
            for (int mt = 0; mt < 2; mt++)
                ldsm4(a[buf][mt], sA + (uint32_t)(aR[mt] * 128 + (((kc + aCb) ^ aR7[mt]) << 4)));
            #pragma unroll
            for (int pp = 0; pp < 2; pp++)
                ldsm4(b[buf][pp], sB + (uint32_t)(bR[pp] * 128 + (((kc + bCb) ^ bR7[pp]) << 4)));
        };

        ldfrag(0, 0);
        #pragma unroll
        for (int t = 0; t < 4; t++) {
            const int cur = t & 1;
            if (t + 1 < 4) ldfrag(t + 1, cur ^ 1);
            #pragma unroll
            for (int mt = 0; mt < 2; mt++)
                #pragma unroll
                for (int nt = 0; nt < 4; nt++)
                    mma_f16(c[mt][nt], a[cur][mt], &b[cur][nt >> 1][(nt & 1) * 2]);
        }

        rd = rd + 1; if (rd >= STAGES) rd -= STAGES;
    }

    // Epilogue (C frag: lane -> row = base + lane>>2 (+8), cols = 2*(lane&3))
    #pragma unroll
    for (int mt = 0; mt < 2; mt++) {
        #pragma unroll
        for (int half = 0; half < 2; half++) {
            int r = wRow + mt * 16 + (lane >> 2) + half * 8;
            int e = e0 + r;
            if (e >= E) continue;
            if (MODE == 1) {
                int bg = g_bidx[e];
                const float* ugr = &g_ug[(size_t)bg * H_DIM + n0];
                __half*      hr  = &g_hh[(size_t)e * H_DIM + n0];
                #pragma unroll
                for (int nt = 0; nt < 4; nt++) {
                    int col = wCol + nt * 8 + (lane & 3) * 2;
                    float2 g = *(const float2*)&ugr[col];
                    float ox = fmaxf(c[mt][nt][half * 2 + 0] + g.x, 0.f);
                    float oy = fmaxf(c[mt][nt][half * 2 + 1] + g.y, 0.f);
                    *(__half2*)&hr[col] = __floats2half2_rn(ox, oy);
                }
            } else {
                float* orow = &out[(size_t)e * DO_DIM + n0];
                #pragma unroll
                for (int nt = 0; nt < 4; nt++) {
                    int col = wCol + nt * 8 + (lane & 3) * 2;
                    float2 bb = *(const float2*)&bias2[col + n0];
                    float2 o;
                    o.x = c[mt][nt][half * 2 + 0] + bb.x;
                    o.y = c[mt][nt][half * 2 + 1] + bb.y;
                    *(float2*)&orow[col] = o;
                }
            }
        }
    }
}

// ---------------------------------------------------------------------------
// Inputs (metadata order): src, dest, edge_attr, u, batch, W1, b1, W2, b2
// ---------------------------------------------------------------------------
extern "C" void kernel_launch(void* const* d_in, const int* in_sizes, int n_in,
                              void* d_out, int out_size) {
    const float* src   = (const float*)d_in[0];
    const float* dest  = (const float*)d_in[1];
    const float* edge  = (const float*)d_in[2];
    const float* u     = (const float*)d_in[3];
    const int*   batch = (const int*)d_in[4];
    const float* W1    = (const float*)d_in[5];
    const float* b1    = (const float*)d_in[6];
    const float* W2    = (const float*)d_in[7];
    const float* b2    = (const float*)d_in[8];
    float* out = (float*)d_out;

    const int E  = in_sizes[4];
    const int EB = (E + BM - 1) / BM;

    static bool attr_set = false;
    if (!attr_set) {
        cudaFuncSetAttribute(mlp_gemm<1>, cudaFuncAttributeMaxDynamicSharedMemorySize, SMEM_BYTES);
        cudaFuncSetAttribute(mlp_gemm<2>, cudaFuncAttributeMaxDynamicSharedMemorySize, SMEM_BYTES);
        attr_set = true;
    }

    bidx_kernel<<<256, 256>>>(batch, E);
    prep_w<<<256, 256>>>(W1, W2);
    ug_kernel<<<dim3(B_GR, 4), 128>>>(u, W1, b1);
    prep_x<<<2048, 256>>>(src, dest, edge, E);

    dim3 g1(H_DIM / BN, EB);     // n-tiles adjacent -> A rows reused in L2
    mlp_gemm<1><<<g1, 256, SMEM_BYTES>>>(nullptr, nullptr, E);

    dim3 g2(DO_DIM / BN, EB);
    mlp_gemm<2><<<g2, 256, SMEM_BYTES>>>(b2, out, E);
}

// round 17
// speedup vs baseline: 1.0818x; 1.0090x over previous
#include <cuda_runtime.h>
#include <cuda_fp16.h>
#include <cstdint>
#include <cstddef>

#define D_IN    256
#define H_DIM   512
#define DO_DIM  256
#define B_GR    64

#define BM  64
#define BN  128
#define BK  64
#define E_MAX 200064
#define NCHUNK 4

#define A_BYTES (BM * BK * 2)                // 8192
#define B_BYTES (BN * BK * 2)                // 16384
#define STAGE_BYTES (A_BYTES + B_BYTES)      // 24576
#define STAGES 3
#define SMEM_BYTES (STAGES * STAGE_BYTES)    // 73728 -> 3 CTAs/SM

// Allocation-free scratch
__device__ __half g_x[(size_t)E_MAX * (3 * D_IN)];    // packed fp16 [src|dest|edge]
__device__ __half g_hh[(size_t)E_MAX * H_DIM];        // fp16 activations
__device__ float  g_ug[B_GR * H_DIM];
__device__ int    g_bidx[E_MAX];
__device__ __half g_w1h[(size_t)H_DIM * (3 * D_IN)];  // W1^T [n=512][k=768] fp16
__device__ __half g_w2h[(size_t)DO_DIM * H_DIM];      // W2^T [n=256][k=512] fp16

__device__ __forceinline__ void mma_f16(float* c, const uint32_t* a, const uint32_t* b) {
    asm volatile(
        "mma.sync.aligned.m16n8k16.row.col.f32.f16.f16.f32 "
        "{%0,%1,%2,%3}, {%4,%5,%6,%7}, {%8,%9}, {%0,%1,%2,%3};\n"
        : "+f"(c[0]), "+f"(c[1]), "+f"(c[2]), "+f"(c[3])
        : "r"(a[0]), "r"(a[1]), "r"(a[2]), "r"(a[3]), "r"(b[0]), "r"(b[1]));
}
__device__ __forceinline__ void ldsm4(uint32_t* r, uint32_t saddr) {
    asm volatile("ldmatrix.sync.aligned.m8n8.x4.shared.b16 {%0,%1,%2,%3}, [%4];"
                 : "=r"(r[0]), "=r"(r[1]), "=r"(r[2]), "=r"(r[3]) : "r"(saddr));
}
__device__ __forceinline__ void cp16(uint32_t saddr, const void* gaddr, uint32_t sz) {
    asm volatile("cp.async.cg.shared.global [%0], [%1], 16, %2;\n"
                 :: "r"(saddr), "l"(gaddr), "r"(sz));
}
__device__ __forceinline__ void cp_commit() { asm volatile("cp.async.commit_group;\n"); }
template <int N>
__device__ __forceinline__ void cp_wait() { asm volatile("cp.async.wait_group %0;\n" :: "n"(N)); }

// ---------------------------------------------------------------------------
// batch index normalization (int32 or int64 source) -> g_bidx
// ---------------------------------------------------------------------------
__global__ void bidx_kernel(const int* __restrict__ batch32, int E) {
    const int tid = threadIdx.x;
    __shared__ int s_is64;
    bool ok = true;
    if (tid < 128) {
        int lo = batch32[2 * tid];
        int hi = batch32[2 * tid + 1];
        ok = (hi == 0) && (lo >= 0) && (lo < B_GR);
    }
    unsigned m = __ballot_sync(0xFFFFFFFFu, ok);
    __shared__ unsigned s_votes[8];
    if ((tid & 31) == 0) s_votes[tid >> 5] = m;
    __syncthreads();
    if (tid == 0) {
        bool all = true;
        for (int w = 0; w < 4; w++) all = all && (s_votes[w] == 0xFFFFFFFFu);
        s_is64 = all ? 1 : 0;
    }
    __syncthreads();
    const int is64 = s_is64;
    for (int e = blockIdx.x * blockDim.x + tid; e < E; e += gridDim.x * blockDim.x) {
        int v = is64 ? batch32[2 * e] : batch32[e];
        g_bidx[e] = v & (B_GR - 1);
    }
}

// ---------------------------------------------------------------------------
// Pack rows [r0, r1) of src|dest|edge into fp16 g_x[e][768]
// ---------------------------------------------------------------------------
__global__ void prep_x(const float* __restrict__ src, const float* __restrict__ dest,
                       const float* __restrict__ edge, int r0, int r1) {
    const int total = (r1 - r0) * (D_IN / 4);
    for (int i = blockIdx.x * blockDim.x + threadIdx.x; i < total;
         i += gridDim.x * blockDim.x) {
        const int e = r0 + (i >> 6);
        const int d = (i & 63) * 4;
        const size_t gs = (size_t)e * D_IN + d;
        const size_t go = (size_t)e * (3 * D_IN) + d;
        float4 v;
        v = *(const float4*)&src[gs];
        *(__half2*)&g_x[go + 0] = __floats2half2_rn(v.x, v.y);
        *(__half2*)&g_x[go + 2] = __floats2half2_rn(v.z, v.w);
        v = *(const float4*)&dest[gs];
        *(__half2*)&g_x[go + 256 + 0] = __floats2half2_rn(v.x, v.y);
        *(__half2*)&g_x[go + 256 + 2] = __floats2half2_rn(v.z, v.w);
        v = *(const float4*)&edge[gs];
        *(__half2*)&g_x[go + 512 + 0] = __floats2half2_rn(v.x, v.y);
        *(__half2*)&g_x[go + 512 + 2] = __floats2half2_rn(v.z, v.w);
    }
}

// ---------------------------------------------------------------------------
// Weight prep: transpose to [n][k] + fp16 round (once; small)
// ---------------------------------------------------------------------------
__global__ void prep_w(const float* __restrict__ W1, const float* __restrict__ W2) {
    const size_t n1 = (size_t)H_DIM * (3 * D_IN);
    const size_t n2 = (size_t)DO_DIM * H_DIM;
    for (size_t i = (size_t)blockIdx.x * blockDim.x + threadIdx.x; i < n1 + n2;
         i += (size_t)gridDim.x * blockDim.x) {
        if (i < n1) {
            int n = (int)(i / (3 * D_IN));
            int k = (int)(i % (3 * D_IN));
            g_w1h[i] = __float2half_rn(W1[(size_t)k * H_DIM + n]);
        } else {
            size_t o = i - n1;
            int n = (int)(o / H_DIM);
            int k = (int)(o % H_DIM);
            g_w2h[o] = __float2half_rn(W2[(size_t)k * DO_DIM + n]);
        }
    }
}

// ---------------------------------------------------------------------------
// ug[b][n] = b1[n] + sum_k u[b][k] * W1[768+k][n]  (fp32)
// ---------------------------------------------------------------------------
__global__ void ug_kernel(const float* __restrict__ u, const float* __restrict__ W1,
                          const float* __restrict__ b1) {
    const int b = blockIdx.x;
    const int n = blockIdx.y * 128 + threadIdx.x;
    __shared__ float us[D_IN];
    for (int i = threadIdx.x; i < D_IN; i += 128) us[i] = u[b * D_IN + i];
    __syncthreads();
    float acc = b1[n];
    #pragma unroll 8
    for (int k = 0; k < D_IN; k++)
        acc += us[k] * W1[(size_t)(3 * D_IN + k) * H_DIM + n];
    g_ug[b * H_DIM + n] = acc;
}

// ---------------------------------------------------------------------------
// FP16 GEMM, CTA 64x128x64, 8 warps (2m x 4n, warp tile 32x32), m16n8k16,
// 3-stage cp.async + single sync per tile + register fragment double buffer,
// XOR-swizzled 128B rows, 3 CTAs/SM.
// MODE 1: h = relu(g_x@W1abc + ug[bidx]) -> g_hh (fp16), rows [eBase, ...)
// MODE 2: out = g_hh @ W2 + b2 (fp32 out)
// ---------------------------------------------------------------------------
template <int MODE>
__global__ void __launch_bounds__(256, 3)
mlp_gemm(const float* __restrict__ bias2, float* __restrict__ out, int E, int eBase) {
    extern __shared__ __half smem[];
    const uint32_t sbase = (uint32_t)__cvta_generic_to_shared(smem);

    const int e0 = eBase + blockIdx.y * BM;
    const int n0 = blockIdx.x * BN;

    const int tid  = threadIdx.x;
    const int lane = tid & 31;
    const int warp = tid >> 5;
    const int wRow = (warp >> 2) * 32;     // 2 m-groups
    const int wCol = (warp & 3) * 32;      // 4 n-groups

    float c[2][4][4];
    #pragma unroll
    for (int mt = 0; mt < 2; mt++)
        #pragma unroll
        for (int nt = 0; nt < 4; nt++)
            #pragma unroll
            for (int i = 0; i < 4; i++) c[mt][nt][i] = 0.f;

    // ldmatrix lane maps (rows are 128B = 64 halves; swizzled chunk = ch ^ (row&7))
    int aR[2], aR7[2];
    #pragma unroll
    for (int mt = 0; mt < 2; mt++) {
        aR[mt]  = wRow + mt * 16 + (lane & 15);
        aR7[mt] = aR[mt] & 7;
    }
    const int aCb = lane >> 4;             // +0 / +1 chunk
    int bR[2], bR7[2];
    #pragma unroll
    for (int pp = 0; pp < 2; pp++) {
        bR[pp]  = wCol + pp * 16 + ((lane & 16) ? 8 : 0) + (lane & 7);
        bR7[pp] = bR[pp] & 7;
    }
    const int bCb = (lane >> 3) & 1;

    // cp.async staging maps (chunks are 16B = 8 halves)
    const int aSRow = tid >> 2;            // 0..63
    const int aSC   = (tid & 3) * 2;       // +j (j<2)
    const int bSRow = tid >> 1;            // 0..127
    const int bSC   = (tid & 1) * 4;       // +j (j<4)

    constexpr int KT   = (MODE == 1) ? (3 * D_IN) / BK : H_DIM / BK;   // 12 / 8
    constexpr int KDIM = (MODE == 1) ? (3 * D_IN) : H_DIM;

    const __half* Ap = (MODE == 1) ? g_x : g_hh;
    const __half* Bp = (MODE == 1) ? g_w1h : g_w2h;

    auto stage = [&](int kt, int slot) {
        const int kg = kt * BK;
        const uint32_t sA = sbase + (uint32_t)slot * STAGE_BYTES;
        const uint32_t sB = sA + A_BYTES;
        #pragma unroll
        for (int j = 0; j < 2; j++) {
            const int ch = aSC + j;
            const uint32_t so = (uint32_t)(aSRow * 128 + (ch ^ (aSRow & 7)) * 16);
            const int e = e0 + aSRow;
            const int ec = (e < E) ? e : 0;
            cp16(sA + so, Ap + (size_t)ec * KDIM + kg + ch * 8, (e < E) ? 16u : 0u);
        }
        #pragma unroll
        for (int j = 0; j < 4; j++) {
            const int ch = bSC + j;
            const uint32_t so = (uint32_t)(bSRow * 128 + (ch ^ (bSRow & 7)) * 16);
            cp16(sB + so, Bp + (size_t)(n0 + bSRow) * KDIM + kg + ch * 8, 16u);
        }
        cp_commit();
    };

    // Prologue: two tiles in flight
    stage(0, 0);
    stage(1, 1);

    int rd = 0;
    for (int kt = 0; kt < KT; kt++) {
        if (kt + 1 < KT) cp_wait<1>();
        else             cp_wait<0>();
        __syncthreads();

        int wr = rd + 2; if (wr >= STAGES) wr -= STAGES;
        if (kt + 2 < KT) stage(kt + 2, wr);

        const uint32_t sA = sbase + (uint32_t)rd * STAGE_BYTES;
        const uint32_t sB = sA + A_BYTES;

        // Register fragment double buffer across the 4 k16 steps
        uint32_t a[2][2][4];   // [buf][mt][4]
        uint32_t b[2][2][4];   // [buf][pp][4]

        auto ldfrag = [&](int t, int buf) {
            const int kc = t * 2;
            #pragma unroll
            for (int mt = 0; mt < 2; mt++)
                ldsm4(a[buf][mt], sA + (uint32_t)(aR[mt] * 128 + (((kc + aCb) ^ aR7[mt]) << 4)));
            #pragma unroll
            for (int pp = 0; pp < 2; pp++)
                ldsm4(b[buf][pp], sB + (uint32_t)(bR[pp] * 128 + (((kc + bCb) ^ bR7[pp]) << 4)));
        };

        ldfrag(0, 0);
        #pragma unroll
        for (int t = 0; t < 4; t++) {
            const int cur = t & 1;
            if (t + 1 < 4) ldfrag(t + 1, cur ^ 1);
            #pragma unroll
            for (int mt = 0; mt < 2; mt++)
                #pragma unroll
                for (int nt = 0; nt < 4; nt++)
                    mma_f16(c[mt][nt], a[cur][mt], &b[cur][nt >> 1][(nt & 1) * 2]);
        }

        rd = rd + 1; if (rd >= STAGES) rd -= STAGES;
    }

    // Epilogue (C frag: lane -> row = base + lane>>2 (+8), cols = 2*(lane&3))
    #pragma unroll
    for (int mt = 0; mt < 2; mt++) {
        #pragma unroll
        for (int half = 0; half < 2; half++) {
            int r = wRow + mt * 16 + (lane >> 2) + half * 8;
            int e = e0 + r;
            if (e >= E) continue;
            if (MODE == 1) {
                int bg = g_bidx[e];
                const float* ugr = &g_ug[(size_t)bg * H_DIM + n0];
                __half*      hr  = &g_hh[(size_t)e * H_DIM + n0];
                #pragma unroll
                for (int nt = 0; nt < 4; nt++) {
                    int col = wCol + nt * 8 + (lane & 3) * 2;
                    float2 g = *(const float2*)&ugr[col];
                    float ox = fmaxf(c[mt][nt][half * 2 + 0] + g.x, 0.f);
                    float oy = fmaxf(c[mt][nt][half * 2 + 1] + g.y, 0.f);
                    *(__half2*)&hr[col] = __floats2half2_rn(ox, oy);
                }
            } else {
                float* orow = &out[(size_t)e * DO_DIM + n0];
                #pragma unroll
                for (int nt = 0; nt < 4; nt++) {
                    int col = wCol + nt * 8 + (lane & 3) * 2;
                    float2 bb = *(const float2*)&bias2[col + n0];
                    float2 o;
                    o.x = c[mt][nt][half * 2 + 0] + bb.x;
                    o.y = c[mt][nt][half * 2 + 1] + bb.y;
                    *(float2*)&orow[col] = o;
                }
            }
        }
    }
}

// ---------------------------------------------------------------------------
// Inputs (metadata order): src, dest, edge_attr, u, batch, W1, b1, W2, b2
// Launch DAG (graph-capturable fork/join):
//   D (main):  bidx, prep_w, ug   ...   gemm1(c) [waits evP[c]] ... gemm2
//   P (side):  prep_x(0..3), evP[c] after each   (overlaps with D)
// ---------------------------------------------------------------------------
extern "C" void kernel_launch(void* const* d_in, const int* in_sizes, int n_in,
                              void* d_out, int out_size) {
    const float* src   = (const float*)d_in[0];
    const float* dest  = (const float*)d_in[1];
    const float* edge  = (const float*)d_in[2];
    const float* u     = (const float*)d_in[3];
    const int*   batch = (const int*)d_in[4];
    const float* W1    = (const float*)d_in[5];
    const float* b1    = (const float*)d_in[6];
    const float* W2    = (const float*)d_in[7];
    const float* b2    = (const float*)d_in[8];
    float* out = (float*)d_out;

    const int E  = in_sizes[4];
    const int EB = (E + BM - 1) / BM;                  // total m-tiles
    const int TPC = (EB + NCHUNK - 1) / NCHUNK;        // m-tiles per chunk

    static bool init_done = false;
    static cudaStream_t sP = nullptr;
    static cudaEvent_t evFork = nullptr;
    static cudaEvent_t evP[NCHUNK];
    if (!init_done) {
        cudaFuncSetAttribute(mlp_gemm<1>, cudaFuncAttributeMaxDynamicSharedMemorySize, SMEM_BYTES);
        cudaFuncSetAttribute(mlp_gemm<2>, cudaFuncAttributeMaxDynamicSharedMemorySize, SMEM_BYTES);
        cudaStreamCreateWithFlags(&sP, cudaStreamNonBlocking);
        cudaEventCreateWithFlags(&evFork, cudaEventDisableTiming);
        for (int c = 0; c < NCHUNK; c++)
            cudaEventCreateWithFlags(&evP[c], cudaEventDisableTiming);
        init_done = true;
    }

    // Fork side stream off the main (captured) stream
    cudaEventRecord(evFork, 0);
    cudaStreamWaitEvent(sP, evFork, 0);

    // Side stream P: chunked fp32->fp16 packing of A
    for (int c = 0; c < NCHUNK; c++) {
        const int r0 = c * TPC * BM;
        int r1 = (c + 1) * TPC * BM; if (r1 > E) r1 = E;
        if (r1 > r0)
            prep_x<<<512, 256, 0, sP>>>(src, dest, edge, r0, r1);
        cudaEventRecord(evP[c], sP);
    }

    // Main stream D: small setup kernels (overlap prep_x chunk 0)
    bidx_kernel<<<256, 256>>>(batch, E);
    prep_w<<<256, 256>>>(W1, W2);
    ug_kernel<<<dim3(B_GR, 4), 128>>>(u, W1, b1);

    // Main stream D: gemm1 chunks, each gated on its prep_x chunk
    for (int c = 0; c < NCHUNK; c++) {
        const int t0 = c * TPC;
        int tc = TPC; if (t0 + tc > EB) tc = EB - t0;
        cudaStreamWaitEvent(0, evP[c], 0);             // also joins P into D
        if (tc > 0) {
            dim3 g1(H_DIM / BN, tc);
            mlp_gemm<1><<<g1, 256, SMEM_BYTES>>>(nullptr, nullptr, E, t0 * BM);
        }
    }

    // gemm2 (full), ordered after all gemm1 chunks on D
    dim3 g2(DO_DIM / BN, EB);
    mlp_gemm<2><<<g2, 256, SMEM_BYTES>>>(b2, out, E, 0);
}